// round 7
// baseline (speedup 1.0000x reference)
#include <cuda_runtime.h>
#include <math.h>

#define PI_HALF 1.57079632679489662f
#define NT 128

// ---------------- scratch (pixel-major [N][B]) ----------------
__device__ float g_y0[729 * 128];
__device__ float g_y1[81 * 128];
__device__ float g_y2[9 * 128];

// Per-sample min/max atomic keys, 128B-padded. Identity 0 for atomicMax.
__device__ unsigned g_kx0[128 * 32];
__device__ unsigned g_kn0[128 * 32];
__device__ unsigned g_kx1[128 * 32];
__device__ unsigned g_kn1[128 * 32];

// ---------------- barriers (all zero-init; self-resetting per use) ----------
__device__ unsigned g_cntA[8 * 32];   // 8 padded sub-counters (tree arrival)
__device__ unsigned g_rootA = 0;
__device__ unsigned g_genA  = 0;
__device__ unsigned g_cntB  = 0, g_genB = 0;
__device__ unsigned g_cntC  = 0, g_genC = 0;

// Barrier A: tree arrival over all nblk blocks. Only blocks with `wait` spin.
__device__ __forceinline__ void barrierA(int bid, int nblk, bool wait)
{
    __threadfence();
    __syncthreads();
    if (threadIdx.x == 0) {
        const unsigned target = *(volatile unsigned*)&g_genA + 1;
        const int r = bid & 7;
        const unsigned ctarget = (unsigned)((nblk - r + 7) >> 3);
        const unsigned a = atomicAdd(&g_cntA[r * 32], 1) + 1;
        if (a == ctarget) {
            g_cntA[r * 32] = 0;
            __threadfence();
            const unsigned ra = atomicAdd(&g_rootA, 1) + 1;
            if (ra == 8) {
                g_rootA = 0;
                __threadfence();
                atomicAdd(&g_genA, 1);
            }
        }
        if (wait)
            while ((int)(*(volatile unsigned*)&g_genA - target) < 0) __nanosleep(32);
        __threadfence();
    }
    __syncthreads();
}

// Simple barrier over `nb` participating blocks.
__device__ __forceinline__ void barrier_small(unsigned* cnt, unsigned* gen,
                                              unsigned nb, bool wait)
{
    __threadfence();
    __syncthreads();
    if (threadIdx.x == 0) {
        const unsigned target = *(volatile unsigned*)gen + 1;
        const unsigned a = atomicAdd(cnt, 1) + 1;
        if (a == nb) {
            *cnt = 0;
            __threadfence();
            atomicAdd(gen, 1);
        }
        if (wait)
            while ((int)(*(volatile unsigned*)gen - target) < 0) __nanosleep(32);
        __threadfence();
    }
    __syncthreads();
}

// ---------------- monotonic float<->uint key ----------------
__device__ __forceinline__ unsigned fkey(float f)
{
    unsigned u = __float_as_uint(f);
    return u ^ ((unsigned)((int)u >> 31) | 0x80000000u);
}
__device__ __forceinline__ float funkey(unsigned k)
{
    unsigned u = (k & 0x80000000u) ? (k ^ 0x80000000u) : ~k;
    return __uint_as_float(u);
}

// ---------------- packed f32x2 FMA ----------------
__device__ __forceinline__ float2 ffma2(float2 a, float2 b, float2 c)
{
    unsigned long long au = *reinterpret_cast<unsigned long long*>(&a);
    unsigned long long bu = *reinterpret_cast<unsigned long long*>(&b);
    unsigned long long cu = *reinterpret_cast<unsigned long long*>(&c);
    unsigned long long du;
    asm("fma.rn.f32x2 %0, %1, %2, %3;" : "=l"(du) : "l"(au), "l"(bu), "l"(cu));
    return *reinterpret_cast<float2*>(&du);
}

// ---------------- cp.async helpers ----------------
__device__ __forceinline__ void cp_async16(float* sdst, const float* gsrc)
{
    unsigned saddr = (unsigned)__cvta_generic_to_shared(sdst);
    asm volatile("cp.async.cg.shared.global [%0], [%1], 16;" :: "r"(saddr), "l"(gsrc));
}
#define CP_COMMIT() asm volatile("cp.async.commit_group;" ::: "memory")
#define CP_WAIT0()  asm volatile("cp.async.wait_group 0;" ::: "memory")

// Serial-core permute: (s,a,p,c) -> s*200 + a*20 + (c/2)*4 + (c%2)*2 + p.
__device__ __forceinline__ int wm_perm(int t)
{
    const int s  = t / 200;
    const int r  = t - s * 200;
    const int a  = r / 20;
    const int r2 = r - a * 20;
    const int p  = r2 / 10;
    const int c  = r2 - p * 10;
    return s * 200 + a * 20 + ((c >> 1) << 2) + ((c & 1) << 1) + p;
}

// Pair-core permute: (s,a,p,c) -> s*200 + role*100 + a*10 + (c%5)*2 + p,
// role = c/5. Each lane's half is a contiguous 100-float (50 float2) slab.
__device__ __forceinline__ int wm_perm_pair(int t)
{
    const int s  = t / 200;
    const int r  = t - s * 200;
    const int a  = r / 20;
    const int r2 = r - a * 20;
    const int p  = r2 / 10;
    const int c  = r2 - p * 10;
    const int role = c / 5;
    const int cp   = c - role * 5;
    return s * 200 + role * 100 + a * 10 + cp * 2 + p;
}

__device__ __forceinline__ void stage_wm_g(const float* __restrict__ gWm,
                                           float* __restrict__ sWm, int tid)
{
    #pragma unroll
    for (int t = tid; t < 1400; t += NT) sWm[wm_perm(t)] = gWm[t];
}
__device__ __forceinline__ void stage_wm_pair_s(const float* __restrict__ sRaw,
                                                float* __restrict__ sWm, int tid)
{
    #pragma unroll
    for (int t = tid; t < 1400; t += NT) sWm[wm_perm_pair(t)] = sRaw[t];
}

// ---------------- serial single-sample core (phase 0) ----------------
__device__ __forceinline__ float mps_core(const float* f,
                                          const float* __restrict__ w0c,
                                          const float* __restrict__ w0s,
                                          const float* __restrict__ sWm,
                                          const float* __restrict__ sWn)
{
    float c0, s0;
    __sincosf(f[0] * PI_HALF, &s0, &c0);
    float v[10];
    #pragma unroll
    for (int a = 0; a < 10; a++)
        v[a] = fmaf(s0, w0s[a], c0 * w0c[a]);

    #pragma unroll
    for (int s = 0; s < 7; s++) {
        float cn, sn;
        __sincosf(f[s + 1] * PI_HALF, &sn, &cn);
        const float4* M = reinterpret_cast<const float4*>(sWm + s * 200);
        float2 acc[10];
        #pragma unroll
        for (int c = 0; c < 10; c++) acc[c] = make_float2(0.f, 0.f);
        #pragma unroll
        for (int a = 0; a < 10; a++) {
            const float2 va2 = make_float2(v[a], v[a]);
            const float4* Ma = M + a * 5;
            #pragma unroll
            for (int j = 0; j < 5; j++) {
                const float4 m = Ma[j];
                acc[2 * j]     = ffma2(va2, make_float2(m.x, m.y), acc[2 * j]);
                acc[2 * j + 1] = ffma2(va2, make_float2(m.z, m.w), acc[2 * j + 1]);
            }
        }
        #pragma unroll
        for (int c = 0; c < 10; c++)
            v[c] = fmaf(sn, acc[c].y, cn * acc[c].x);
    }

    float ce, se;
    __sincosf(f[8] * PI_HALF, &se, &ce);
    float r = 0.f;
    #pragma unroll
    for (int a = 0; a < 10; a++)
        r = fmaf(v[a], fmaf(se, sWn[2 * a + 1], ce * sWn[2 * a]), r);
    return r;
}

// ---------------- pair core (tail phases) ----------------
// Lane pair (2k, 2k+1) shares one sample; role = lane&1 owns c-half role*5..+4.
// Per step: 50 FFMA2 + ~30 LDS + 5 shfl.xor(1) to re-assemble full v.
__device__ __forceinline__ float mps_core_pair(const float* f, int role,
                                               const float* __restrict__ w0c,
                                               const float* __restrict__ w0s,
                                               const float* __restrict__ sWm,
                                               const float* __restrict__ sWn)
{
    float c0, s0;
    __sincosf(f[0] * PI_HALF, &s0, &c0);
    float v[10];
    #pragma unroll
    for (int a = 0; a < 10; a++)
        v[a] = fmaf(s0, w0s[a], c0 * w0c[a]);

    #pragma unroll
    for (int s = 0; s < 7; s++) {
        float cn, sn;
        __sincosf(f[s + 1] * PI_HALF, &sn, &cn);
        const float2* M = reinterpret_cast<const float2*>(sWm + s * 200 + role * 100);
        float2 acc[5];
        #pragma unroll
        for (int j = 0; j < 5; j++) acc[j] = make_float2(0.f, 0.f);
        #pragma unroll
        for (int a = 0; a < 10; a++) {
            const float2 va2 = make_float2(v[a], v[a]);
            const float2* Ma = M + a * 5;
            #pragma unroll
            for (int j = 0; j < 5; j++)
                acc[j] = ffma2(va2, Ma[j], acc[j]);
        }
        float vh[5];
        #pragma unroll
        for (int j = 0; j < 5; j++)
            vh[j] = fmaf(sn, acc[j].y, cn * acc[j].x);
        #pragma unroll
        for (int j = 0; j < 5; j++) {
            const float other = __shfl_xor_sync(0xFFFFFFFFu, vh[j], 1);
            v[j]     = role ? other : vh[j];
            v[5 + j] = role ? vh[j] : other;
        }
    }

    float ce, se;
    __sincosf(f[8] * PI_HALF, &se, &ce);
    float r = 0.f;
    #pragma unroll
    for (int a = 0; a < 10; a++)
        r = fmaf(v[a], fmaf(se, sWn[2 * a + 1], ce * sWn[2 * a]), r);
    return r;
}

// ---------------- single fused kernel ----------------
__global__ void __launch_bounds__(NT, 5)
fused_lotenet(const float* __restrict__ x,
              const float* __restrict__ W00, const float* __restrict__ Wm0, const float* __restrict__ Wn0,
              const float* __restrict__ W01, const float* __restrict__ Wm1, const float* __restrict__ Wn1,
              const float* __restrict__ W02, const float* __restrict__ Wm2, const float* __restrict__ Wn2,
              const float* __restrict__ W03, const float* __restrict__ Wm3, const float* __restrict__ Wn3,
              float* __restrict__ out)
{
    __shared__ __align__(16) float sWm[1400];
    __shared__ __align__(16) float sRaw[1664];
    __shared__ __align__(16) float sW0[200];
    __shared__ float sWn[20];

    const int tid = threadIdx.x;
    const int bid = blockIdx.x;
    const int nblk = gridDim.x;

    float f[9];

    // ---- Phase 0: layer-0 MPS, one pixel per block (single wave) ----
    for (int n = bid; n < 729; n += nblk) {
        __syncthreads();
        const int i = n / 27, j = n - i * 27;
        #pragma unroll
        for (int k = 0; k < 9; k++) {              // inputs issued first: overlap
            const int r = 3 * i + k / 3;
            const int c = 3 * j + (k - (k / 3) * 3);
            f[k] = x[((size_t)tid * 81 + r) * 81 + c];
        }
        stage_wm_g(Wm0 + n * 1400, sWm, tid);
        if (tid < 20)      sW0[tid]      = W00[n * 20 + tid];
        else if (tid < 40) sWn[tid - 20] = Wn0[n * 20 + (tid - 20)];
        __syncthreads();

        const float y = mps_core(f, sW0, sW0 + 10, sWm, sWn);
        g_y0[n * 128 + tid] = y;
        atomicMax(&g_kx0[tid * 32], fkey(y));
        atomicMax(&g_kn0[tid * 32], ~fkey(y));
    }

    // Prefetch phase-1 weights (blocks 0..161; pixel = bid>>1).
    if (bid < 162) {
        const float* gWm = Wm1 + (bid >> 1) * 1400;
        const float* gW0 = W01 + (bid >> 1) * 20;
        const float* gWn = Wn1 + (bid >> 1) * 20;
        #pragma unroll
        for (int t = tid; t < 360; t += NT) {
            if (t < 350)      cp_async16(sRaw + t * 4,                gWm + t * 4);
            else if (t < 355) cp_async16(sRaw + 1400 + (t - 350) * 4, gW0 + (t - 350) * 4);
            else              cp_async16(sRaw + 1420 + (t - 355) * 4, gWn + (t - 355) * 4);
        }
        CP_COMMIT();
    }
    barrierA(bid, nblk, bid < 162);
    if (bid >= 162) return;                        // not needed any more

    // ---- Phase 1: layer-1 MPS. 162 blocks; sample shared by lane pair ----
    {
        CP_WAIT0();
        __syncthreads();
        stage_wm_pair_s(sRaw, sWm, tid);
        if (tid < 20)      sW0[tid]      = sRaw[1400 + tid];
        else if (tid < 40) sWn[tid - 20] = sRaw[1420 + (tid - 20)];

        const int n = bid >> 1;
        const int b = ((bid & 1) << 6) + (tid >> 1);
        const int role = tid & 1;

        const float mn = funkey(~g_kn0[b * 32]);
        const float iv = 1.0f / (funkey(g_kx0[b * 32]) - mn);
        __syncthreads();

        const int i = n / 9, j = n - i * 9;
        #pragma unroll
        for (int k = 0; k < 9; k++) {
            const int r = 3 * i + k / 3;
            const int c = 3 * j + (k - (k / 3) * 3);
            f[k] = (g_y0[(r * 27 + c) * 128 + b] - mn) * iv;
        }
        const float y = mps_core_pair(f, role, sW0, sW0 + 10, sWm, sWn);
        if (role == 0) {
            g_y1[n * 128 + b] = y;
            atomicMax(&g_kx1[b * 32], fkey(y));
            atomicMax(&g_kn1[b * 32], ~fkey(y));
        }

        // Prefetch phase-2 weights (blocks 0..17; pixel = bid>>1).
        if (bid < 18) {
            __syncthreads();
            const float* gWm = Wm2 + (bid >> 1) * 1400;
            const float* gW0 = W02 + (bid >> 1) * 20;
            const float* gWn = Wn2 + (bid >> 1) * 20;
            #pragma unroll
            for (int t = tid; t < 360; t += NT) {
                if (t < 350)      cp_async16(sRaw + t * 4,                gWm + t * 4);
                else if (t < 355) cp_async16(sRaw + 1400 + (t - 350) * 4, gW0 + (t - 350) * 4);
                else              cp_async16(sRaw + 1420 + (t - 355) * 4, gWn + (t - 355) * 4);
            }
            CP_COMMIT();
        }
    }
    barrier_small(&g_cntB, &g_genB, 162, bid < 21);
    if (bid >= 21) return;                         // keep only 21 blocks

    // ---- Phase 2: layer-2 MPS. 18 blocks; block 18 resets L0 keys ----
    if (bid < 18) {
        CP_WAIT0();
        __syncthreads();
        stage_wm_pair_s(sRaw, sWm, tid);
        if (tid < 20)      sW0[tid]      = sRaw[1400 + tid];
        else if (tid < 40) sWn[tid - 20] = sRaw[1420 + (tid - 20)];

        const int n = bid >> 1;
        const int b = ((bid & 1) << 6) + (tid >> 1);
        const int role = tid & 1;

        const float mn = funkey(~g_kn1[b * 32]);
        const float iv = 1.0f / (funkey(g_kx1[b * 32]) - mn);
        __syncthreads();

        const int i = n / 3, j = n - i * 3;
        #pragma unroll
        for (int k = 0; k < 9; k++) {
            const int r = 3 * i + k / 3;
            const int c = 3 * j + (k - (k / 3) * 3);
            f[k] = (g_y1[(r * 9 + c) * 128 + b] - mn) * iv;
        }
        const float y = mps_core_pair(f, role, sW0, sW0 + 10, sWm, sWn);
        if (role == 0) g_y2[n * 128 + b] = y;
    } else if (bid == 18) {
        g_kx0[tid * 32] = 0;
        g_kn0[tid * 32] = 0;
    }
    // Prefetch final-layer weights (blocks 0..19).
    if (bid < 20) {
        __syncthreads();
        #pragma unroll
        for (int t = tid; t < 405; t += NT) {
            if (t < 350)      cp_async16(sRaw + t * 4,                Wm3 + t * 4);
            else if (t < 400) cp_async16(sRaw + 1400 + (t - 350) * 4, W03 + (t - 350) * 4);
            else              cp_async16(sRaw + 1600 + (t - 400) * 4, Wn3 + (t - 400) * 4);
        }
        CP_COMMIT();
    }
    barrier_small(&g_cntC, &g_genC, 21, true);

    // ---- Phase 3: final MPS (O=10). 20 blocks; block 20 resets L1 keys ----
    if (bid < 20) {
        CP_WAIT0();
        __syncthreads();
        stage_wm_pair_s(sRaw, sWm, tid);
        #pragma unroll
        for (int t = tid; t < 200; t += NT) sW0[t] = sRaw[1400 + t];
        if (tid < 20) sWn[tid] = sRaw[1600 + tid];

        const int o = bid >> 1;
        const int b = ((bid & 1) << 6) + (tid >> 1);
        const int role = tid & 1;

        float yk[9];
        float mn = INFINITY, mx = -INFINITY;
        #pragma unroll
        for (int k = 0; k < 9; k++) {
            yk[k] = g_y2[k * 128 + b];
            mn = fminf(mn, yk[k]);
            mx = fmaxf(mx, yk[k]);
        }
        const float iv = 1.0f / (mx - mn);
        __syncthreads();

        #pragma unroll
        for (int k = 0; k < 9; k++) f[k] = (yk[k] - mn) * iv;

        const float y = mps_core_pair(f, role, sW0 + o * 10, sW0 + 100 + o * 10, sWm, sWn);
        if (role == 0) out[b * 10 + o] = y;
    } else {                                       // bid == 20
        g_kx1[tid * 32] = 0;
        g_kn1[tid * 32] = 0;
    }
}

extern "C" void kernel_launch(void* const* d_in, const int* in_sizes, int n_in,
                              void* d_out, int out_size)
{
    const float* x   = (const float*)d_in[0];
    const float* W00 = (const float*)d_in[1];
    const float* Wm0 = (const float*)d_in[2];
    const float* Wn0 = (const float*)d_in[3];
    const float* W01 = (const float*)d_in[6];
    const float* Wm1 = (const float*)d_in[7];
    const float* Wn1 = (const float*)d_in[8];
    const float* W02 = (const float*)d_in[11];
    const float* Wm2 = (const float*)d_in[12];
    const float* Wn2 = (const float*)d_in[13];
    const float* W03 = (const float*)d_in[16];
    const float* Wm3 = (const float*)d_in[17];
    const float* Wn3 = (const float*)d_in[18];

    int nsm = 148;
    cudaDeviceGetAttribute(&nsm, cudaDevAttrMultiProcessorCount, 0);
    const int grid = 5 * nsm;   // __launch_bounds__(128,5): all resident

    fused_lotenet<<<grid, NT>>>(x, W00, Wm0, Wn0, W01, Wm1, Wn1,
                                W02, Wm2, Wn2, W03, Wm3, Wn3,
                                (float*)d_out);
}